// round 16
// baseline (speedup 1.0000x reference)
#include <cuda_runtime.h>
#include <cuda_fp16.h>
#include <math.h>
#include <stdint.h>
#include <float.h>

// VQ_Layer — int8 mma.sync filter + exact fp32 refine (warp-cooperative IO).
// Filter identical to R15 (passing, 273.8us). Refine rewritten: all row-granular
// global traffic (input rows, candidate rows, best-row epilogue) is staged
// through smem with warp-cooperative coalesced loads; the bit-exact sequential
// chains read bit-copied values from smem, so arithmetic is unchanged.

typedef unsigned long long ull;

#define N_ROWS 131072
#define D 64
#define K_CODES 1024
#define QOFF (N_ROWS * D)

#define F_THREADS 128
#define F_ROWS 64
#define F_BLOCKS (N_ROWS / F_ROWS)         // 2048
#define CHUNK 128
#define NCHUNK (K_CODES / CHUNK)           // 8
#define BPITCH 20
#define CAND_CAP 32
#define EPS2 0.1f

#define R_THREADS 256
#define R_BLOCKS (N_ROWS / R_THREADS)      // 512
#define RPITCH 68                          // floats per staged row (272B, 16B-aligned, phase-conflict-free)
#define R_SMEM (8 * 32 * RPITCH * 4)       // 69632 bytes dynamic

// ---- device scratch ----
__device__ float g_norms[K_CODES];
__device__ int   g_hist[K_CODES];
__device__ float g_partial[R_BLOCKS];
__device__ unsigned short g_cand[CAND_CAP * N_ROWS];
__device__ int   g_cnt[N_ROWS];
__device__ uint32_t g_qx[N_ROWS * 16];
__device__ uint32_t g_qe[K_CODES * 16];
__device__ int   g_amax_x;
__device__ int   g_amax_e;

// ---- helpers ----
__device__ __forceinline__ void mma_s8(int c[4], uint32_t a0, uint32_t a1,
                                       uint32_t a2, uint32_t a3,
                                       uint32_t b0, uint32_t b1) {
    asm("mma.sync.aligned.m16n8k32.row.col.s32.s8.s8.s32 "
        "{%0,%1,%2,%3}, {%4,%5,%6,%7}, {%8,%9}, {%0,%1,%2,%3};"
        : "+r"(c[0]), "+r"(c[1]), "+r"(c[2]), "+r"(c[3])
        : "r"(a0), "r"(a1), "r"(a2), "r"(a3), "r"(b0), "r"(b1));
}
__device__ __forceinline__ uint32_t pack_s8x4(float a, float b, float c, float d,
                                              float sinv) {
    int q0 = max(-127, min(127, __float2int_rn(a * sinv)));
    int q1 = max(-127, min(127, __float2int_rn(b * sinv)));
    int q2 = max(-127, min(127, __float2int_rn(c * sinv)));
    int q3 = max(-127, min(127, __float2int_rn(d * sinv)));
    return (uint32_t)(q0 & 0xFF) | ((uint32_t)(q1 & 0xFF) << 8)
         | ((uint32_t)(q2 & 0xFF) << 16) | ((uint32_t)(q3 & 0xFF) << 24);
}

// ---- exact-arithmetic helpers (R5-verified reference numerics) ----
__device__ __forceinline__ float exact_asq(const float4* x) {
    float s = 0.f;
    #pragma unroll
    for (int i = 0; i < 16; i++) {
        float4 v = x[i];
        s = __fadd_rn(s, __fmul_rn(v.x, v.x));
        s = __fadd_rn(s, __fmul_rn(v.y, v.y));
        s = __fadd_rn(s, __fmul_rn(v.z, v.z));
        s = __fadd_rn(s, __fmul_rn(v.w, v.w));
    }
    return s;
}
__device__ __forceinline__ float exact_dot(const float4* x, const float4* e) {
    float d = 0.f;
    #pragma unroll
    for (int j = 0; j < 16; j++) {
        float4 ev = e[j];
        float4 xv = x[j];
        d = __fmaf_rn(xv.x, ev.x, d);
        d = __fmaf_rn(xv.y, ev.y, d);
        d = __fmaf_rn(xv.z, ev.z, d);
        d = __fmaf_rn(xv.w, ev.w, d);
    }
    return d;
}

// ---- kernel 1: fused init — reset counters/hist, amax_x, code norms + amax_e ----
__global__ void vq_init_kernel(const float* __restrict__ inp,
                               const float* __restrict__ emb) {
    int i = blockIdx.x * blockDim.x + threadIdx.x;   // grid 1024*256 = 262144
    if (i < N_ROWS) g_cnt[i] = 0;
    if (i < K_CODES) {
        g_hist[i] = 0;
        const float4* e = (const float4*)(emb + (size_t)i * D);
        float s = 0.f, m = 0.f;
        #pragma unroll
        for (int j = 0; j < 16; j++) {
            float4 v = e[j];
            s = __fadd_rn(s, __fmul_rn(v.x, v.x));
            s = __fadd_rn(s, __fmul_rn(v.y, v.y));
            s = __fadd_rn(s, __fmul_rn(v.z, v.z));
            s = __fadd_rn(s, __fmul_rn(v.w, v.w));
            m = fmaxf(m, fmaxf(fmaxf(fabsf(v.x), fabsf(v.y)),
                               fmaxf(fabsf(v.z), fabsf(v.w))));
        }
        g_norms[i] = s;
        atomicMax(&g_amax_e, __float_as_int(m));
    }
    if (i == 0) { /* amaxes pre-cleared by first warp below via atomics on 0-init */ }
    // amax_x over the full input (strided)
    const float4* p = (const float4*)inp;
    float m = 0.f;
    for (int j = i; j < N_ROWS * D / 4; j += gridDim.x * blockDim.x) {
        float4 v = p[j];
        m = fmaxf(m, fmaxf(fmaxf(fabsf(v.x), fabsf(v.y)),
                           fmaxf(fabsf(v.z), fabsf(v.w))));
    }
    #pragma unroll
    for (int o = 16; o > 0; o >>= 1)
        m = fmaxf(m, __shfl_xor_sync(0xffffffffu, m, o));
    if ((threadIdx.x & 31) == 0) atomicMax(&g_amax_x, __float_as_int(m));
}
// amax accumulators must start at <= any value each run: clear in tiny kernel
__global__ void vq_clear_amax_kernel() {
    if (threadIdx.x == 0) { g_amax_x = 0; g_amax_e = 0; }
}

// ---- kernel 2: fused quantize x + e ----
__global__ void vq_quant_kernel(const float* __restrict__ inp,
                                const float* __restrict__ emb) {
    int w = blockIdx.x * blockDim.x + threadIdx.x;
    if (w < N_ROWS * 16) {
        float amax = fmaxf(__int_as_float(g_amax_x), 1e-20f);
        float sinv = 127.f / amax;
        float4 v = ((const float4*)inp)[w];
        g_qx[w] = pack_s8x4(v.x, v.y, v.z, v.w, sinv);
    } else {
        int u = w - N_ROWS * 16;
        if (u < K_CODES * 16) {
            float amax = fmaxf(__int_as_float(g_amax_e), 1e-20f);
            float sinv = 127.f / amax;
            float4 v = ((const float4*)emb)[u];
            g_qe[u] = pack_s8x4(v.x, v.y, v.z, v.w, sinv);
        }
    }
}

// ---- kernel 3: s8 mma filter (byte-identical logic to R15) ----
__global__ __launch_bounds__(F_THREADS) void vq_filter_kernel() {
    __shared__ uint32_t shB[CHUNK * BPITCH];
    __shared__ float sh_bn[K_CODES];

    const int tid = threadIdx.x;
    const int lane = tid & 31;
    const int w = tid >> 5;
    const int gq = lane >> 2;
    const int tq = lane & 3;
    const int grow0 = blockIdx.x * F_ROWS + w * 16 + gq;
    const int grow1 = grow0 + 8;

    for (int i = tid; i < K_CODES; i += F_THREADS) sh_bn[i] = g_norms[i];

    const float sx = fmaxf(__int_as_float(g_amax_x), 1e-20f) * (1.f / 127.f);
    const float se = fmaxf(__int_as_float(g_amax_e), 1e-20f) * (1.f / 127.f);
    const float f = 2.f * sx * se;

    uint32_t A0[2][2], A1[2][2];
    #pragma unroll
    for (int ks = 0; ks < 2; ks++) {
        A0[ks][0] = g_qx[grow0 * 16 + ks * 8 + tq];
        A0[ks][1] = g_qx[grow1 * 16 + ks * 8 + tq];
        A1[ks][0] = g_qx[grow0 * 16 + ks * 8 + 4 + tq];
        A1[ks][1] = g_qx[grow1 * 16 + ks * 8 + 4 + tq];
    }

    float best0 = FLT_MAX, best1 = FLT_MAX;

    for (int ch = 0; ch < NCHUNK; ch++) {
        __syncthreads();
        {
            const uint4* src = (const uint4*)&g_qe[(ch * CHUNK + tid) * 16];
            uint32_t* dst = &shB[tid * BPITCH];
            #pragma unroll
            for (int i = 0; i < 4; i++)
                *(uint4*)(dst + 4 * i) = src[i];
        }
        __syncthreads();

        int c[16][4];
        #pragma unroll
        for (int nt = 0; nt < 16; nt++)
            c[nt][0] = c[nt][1] = c[nt][2] = c[nt][3] = 0;

        #pragma unroll
        for (int ks = 0; ks < 2; ks++) {
            #pragma unroll
            for (int nt = 0; nt < 16; nt++) {
                int n = nt * 8 + gq;
                uint32_t b0 = shB[n * BPITCH + ks * 8 + tq];
                uint32_t b1 = shB[n * BPITCH + ks * 8 + 4 + tq];
                mma_s8(c[nt], A0[ks][0], A0[ks][1], A1[ks][0], A1[ks][1], b0, b1);
            }
        }

        const int cbase = ch * CHUNK;
        float sc[16][4];
        float m0 = FLT_MAX, m1 = FLT_MAX;
        #pragma unroll
        for (int nt = 0; nt < 16; nt++) {
            int col0 = cbase + nt * 8 + 2 * tq;
            float bn0 = sh_bn[col0], bn1 = sh_bn[col0 + 1];
            float s00 = fmaf(-f, (float)c[nt][0], bn0);
            float s01 = fmaf(-f, (float)c[nt][1], bn1);
            float s10 = fmaf(-f, (float)c[nt][2], bn0);
            float s11 = fmaf(-f, (float)c[nt][3], bn1);
            sc[nt][0] = s00; sc[nt][1] = s01; sc[nt][2] = s10; sc[nt][3] = s11;
            m0 = fminf(m0, fminf(s00, s01));
            m1 = fminf(m1, fminf(s10, s11));
        }
        m0 = fminf(m0, __shfl_xor_sync(0xffffffffu, m0, 1));
        m0 = fminf(m0, __shfl_xor_sync(0xffffffffu, m0, 2));
        m1 = fminf(m1, __shfl_xor_sync(0xffffffffu, m1, 1));
        m1 = fminf(m1, __shfl_xor_sync(0xffffffffu, m1, 2));
        best0 = fminf(best0, m0);
        best1 = fminf(best1, m1);
        const float th0 = best0 + EPS2;
        const float th1 = best1 + EPS2;

        #pragma unroll
        for (int nt = 0; nt < 16; nt++) {
            int col0 = cbase + nt * 8 + 2 * tq;
            if (sc[nt][0] <= th0) {
                int s = atomicAdd(&g_cnt[grow0], 1);
                if (s < CAND_CAP) g_cand[s * N_ROWS + grow0] = (unsigned short)col0;
            }
            if (sc[nt][1] <= th0) {
                int s = atomicAdd(&g_cnt[grow0], 1);
                if (s < CAND_CAP) g_cand[s * N_ROWS + grow0] = (unsigned short)(col0 + 1);
            }
            if (sc[nt][2] <= th1) {
                int s = atomicAdd(&g_cnt[grow1], 1);
                if (s < CAND_CAP) g_cand[s * N_ROWS + grow1] = (unsigned short)col0;
            }
            if (sc[nt][3] <= th1) {
                int s = atomicAdd(&g_cnt[grow1], 1);
                if (s < CAND_CAP) g_cand[s * N_ROWS + grow1] = (unsigned short)(col0 + 1);
            }
        }
    }
}

// ---- kernel 4: exact refine, warp-cooperative IO ----
__global__ __launch_bounds__(R_THREADS) void vq_refine_kernel(
    const float* __restrict__ inp,
    const float* __restrict__ emb,
    float* __restrict__ out)
{
    extern __shared__ float sbuf[];            // 8 warps * 32 rows * RPITCH
    __shared__ float sh_red[R_THREADS];

    const int tid = threadIdx.x;
    const int lane = tid & 31;
    const int wrp = tid >> 5;
    const int r = blockIdx.x * R_THREADS + tid;
    const int rb = blockIdx.x * R_THREADS + wrp * 32;   // warp's first row
    float* buf = sbuf + wrp * 32 * RPITCH;
    const unsigned FULL = 0xffffffffu;

    // 1) cooperative, coalesced load of this warp's 32 input rows
    for (int l = 0; l < 32; l++) {
        float2 v = *(const float2*)(inp + (size_t)(rb + l) * D + lane * 2);
        *(float2*)(buf + l * RPITCH + lane * 2) = v;
    }
    __syncwarp(FULL);
    float4 x[16];
    #pragma unroll
    for (int i = 0; i < 16; i++)
        x[i] = *(const float4*)(buf + lane * RPITCH + i * 4);
    __syncwarp(FULL);

    const float asq = exact_asq(x);

    int bi = K_CODES;
    float best = FLT_MAX;
    const int cnt = g_cnt[r];
    const bool ovf = (cnt > CAND_CAP);
    const int ccnt = ovf ? 0 : cnt;

    int rounds = ccnt;
    #pragma unroll
    for (int o = 16; o > 0; o >>= 1)
        rounds = max(rounds, __shfl_xor_sync(FULL, rounds, o));

    for (int i = 0; i < rounds; i++) {
        int myc = (i < ccnt) ? (int)g_cand[i * N_ROWS + r] : -1;
        // cooperative staging of each lane's candidate row
        for (int l = 0; l < 32; l++) {
            int c = __shfl_sync(FULL, myc, l);
            if (c >= 0) {
                float2 v = *(const float2*)(emb + (size_t)c * D + lane * 2);
                *(float2*)(buf + l * RPITCH + lane * 2) = v;
            }
        }
        __syncwarp(FULL);
        if (myc >= 0) {
            const float4* e = (const float4*)(buf + lane * RPITCH);
            float dot = exact_dot(x, e);
            float dist = __fadd_rn(__fmaf_rn(-2.f, dot, asq), g_norms[myc]);
            if (dist < best || (dist == best && myc < bi)) { best = dist; bi = myc; }
        }
        __syncwarp(FULL);
    }

    if (ovf) {
        // exact full scan, ascending (first-index ties); rare
        best = FLT_MAX; bi = K_CODES;
        for (int c = 0; c < K_CODES; c++) {
            float dot = exact_dot(x, (const float4*)(emb + (size_t)c * D));
            float dist = __fadd_rn(__fmaf_rn(-2.f, dot, asq), g_norms[c]);
            if (dist < best) { best = dist; bi = c; }
        }
    }

    // 2) epilogue: cooperative staging of best rows, loss from smem, coalesced store
    __syncwarp(FULL);
    for (int l = 0; l < 32; l++) {
        int c = __shfl_sync(FULL, bi, l);
        float2 v = *(const float2*)(emb + (size_t)c * D + lane * 2);
        *(float2*)(buf + l * RPITCH + lane * 2) = v;
    }
    __syncwarp(FULL);

    float ls = 0.f;
    {
        const float4* q4 = (const float4*)(buf + lane * RPITCH);
        #pragma unroll
        for (int i = 0; i < 16; i++) {
            float4 q = q4[i];
            float4 v = x[i];
            float d0 = v.x - q.x, d1 = v.y - q.y, d2 = v.z - q.z, d3 = v.w - q.w;
            ls = fmaf(d0, d0, ls); ls = fmaf(d1, d1, ls);
            ls = fmaf(d2, d2, ls); ls = fmaf(d3, d3, ls);
        }
    }
    // coalesced quantized-row store from the staged buffer
    for (int l = 0; l < 32; l++) {
        float2 v = *(const float2*)(buf + l * RPITCH + lane * 2);
        *(float2*)(out + (size_t)(rb + l) * D + lane * 2) = v;
    }
    out[QOFF + r] = (float)bi;
    atomicAdd(&g_hist[bi], 1);

    sh_red[tid] = ls;
    __syncthreads();
    for (int s = R_THREADS / 2; s > 0; s >>= 1) {
        if (tid < s) sh_red[tid] += sh_red[tid + s];
        __syncthreads();
    }
    if (tid == 0) g_partial[blockIdx.x] = sh_red[0];
}

// ---- kernel 5: perplexity + vq_loss ----
__global__ void vq_final_kernel(float* __restrict__ out) {
    __shared__ float sh[1024];
    const int t = threadIdx.x;

    float p = (float)g_hist[t] * (1.0f / (float)N_ROWS);
    sh[t] = p * logf(p + 1e-10f);
    __syncthreads();
    for (int s = 512; s > 0; s >>= 1) {
        if (t < s) sh[t] += sh[t + s];
        __syncthreads();
    }
    float ent = sh[0];
    __syncthreads();

    sh[t] = (t < R_BLOCKS) ? g_partial[t] : 0.f;
    __syncthreads();
    for (int s = 512; s > 0; s >>= 1) {
        if (t < s) sh[t] += sh[t + s];
        __syncthreads();
    }

    if (t == 0) {
        float m = sh[0] / (float)((size_t)N_ROWS * D);
        out[QOFF + N_ROWS]     = expf(-ent);       // perplexity
        out[QOFF + N_ROWS + 1] = m + 0.25f * m;    // commitment + beta*codebook
    }
}

extern "C" void kernel_launch(void* const* d_in, const int* in_sizes, int n_in,
                              void* d_out, int out_size) {
    const float* inp = (const float*)d_in[0];   // [131072, 64]
    const float* emb = (const float*)d_in[1];   // [1024, 64]
    float* out = (float*)d_out;

    cudaFuncSetAttribute(vq_refine_kernel,
                         cudaFuncAttributeMaxDynamicSharedMemorySize, R_SMEM);

    vq_clear_amax_kernel<<<1, 32>>>();
    vq_init_kernel<<<1024, 256>>>(inp, emb);
    vq_quant_kernel<<<8256, 256>>>(inp, emb);
    vq_filter_kernel<<<F_BLOCKS, F_THREADS>>>();
    vq_refine_kernel<<<R_BLOCKS, R_THREADS, R_SMEM>>>(inp, emb, out);
    vq_final_kernel<<<1, 1024>>>(out);
}

// round 17
// speedup vs baseline: 1.0661x; 1.0661x over previous
#include <cuda_runtime.h>
#include <cuda_fp16.h>
#include <math.h>
#include <stdint.h>
#include <float.h>

// VQ_Layer — int8 mma.sync filter (CHUNK=64, high-occupancy) + exact fp32
// refine (warp-cooperative IO). R16 ncu showed the filter is issue/occupancy
// bound (tensor 8.9%, occ 27.5%, 96 regs). This round halves the per-thread
// accumulator tile (c[8][4]=32 regs) and stores scores in place (bit-cast into
// the accumulator regs) to hit 8 blocks/SM.

typedef unsigned long long ull;

#define N_ROWS 131072
#define D 64
#define K_CODES 1024
#define QOFF (N_ROWS * D)

#define F_THREADS 128
#define F_ROWS 64
#define F_BLOCKS (N_ROWS / F_ROWS)         // 2048
#define CHUNK 64
#define NCHUNK (K_CODES / CHUNK)           // 16
#define BPITCH 20
#define CAND_CAP 32
#define EPS2 0.1f

#define R_THREADS 256
#define R_BLOCKS (N_ROWS / R_THREADS)      // 512
#define RPITCH 68
#define R_SMEM (8 * 32 * RPITCH * 4)       // 69632 bytes dynamic

// ---- device scratch ----
__device__ float g_norms[K_CODES];
__device__ int   g_hist[K_CODES];
__device__ float g_partial[R_BLOCKS];
__device__ unsigned short g_cand[CAND_CAP * N_ROWS];
__device__ int   g_cnt[N_ROWS];
__device__ uint32_t g_qx[N_ROWS * 16];
__device__ uint32_t g_qe[K_CODES * 16];
__device__ int   g_amax_x;
__device__ int   g_amax_e;

// ---- helpers ----
__device__ __forceinline__ void mma_s8(int c[4], uint32_t a0, uint32_t a1,
                                       uint32_t a2, uint32_t a3,
                                       uint32_t b0, uint32_t b1) {
    asm("mma.sync.aligned.m16n8k32.row.col.s32.s8.s8.s32 "
        "{%0,%1,%2,%3}, {%4,%5,%6,%7}, {%8,%9}, {%0,%1,%2,%3};"
        : "+r"(c[0]), "+r"(c[1]), "+r"(c[2]), "+r"(c[3])
        : "r"(a0), "r"(a1), "r"(a2), "r"(a3), "r"(b0), "r"(b1));
}
__device__ __forceinline__ uint32_t pack_s8x4(float a, float b, float c, float d,
                                              float sinv) {
    int q0 = max(-127, min(127, __float2int_rn(a * sinv)));
    int q1 = max(-127, min(127, __float2int_rn(b * sinv)));
    int q2 = max(-127, min(127, __float2int_rn(c * sinv)));
    int q3 = max(-127, min(127, __float2int_rn(d * sinv)));
    return (uint32_t)(q0 & 0xFF) | ((uint32_t)(q1 & 0xFF) << 8)
         | ((uint32_t)(q2 & 0xFF) << 16) | ((uint32_t)(q3 & 0xFF) << 24);
}

// ---- exact-arithmetic helpers (R5-verified reference numerics) ----
__device__ __forceinline__ float exact_asq(const float4* x) {
    float s = 0.f;
    #pragma unroll
    for (int i = 0; i < 16; i++) {
        float4 v = x[i];
        s = __fadd_rn(s, __fmul_rn(v.x, v.x));
        s = __fadd_rn(s, __fmul_rn(v.y, v.y));
        s = __fadd_rn(s, __fmul_rn(v.z, v.z));
        s = __fadd_rn(s, __fmul_rn(v.w, v.w));
    }
    return s;
}
__device__ __forceinline__ float exact_dot(const float4* x, const float4* e) {
    float d = 0.f;
    #pragma unroll
    for (int j = 0; j < 16; j++) {
        float4 ev = e[j];
        float4 xv = x[j];
        d = __fmaf_rn(xv.x, ev.x, d);
        d = __fmaf_rn(xv.y, ev.y, d);
        d = __fmaf_rn(xv.z, ev.z, d);
        d = __fmaf_rn(xv.w, ev.w, d);
    }
    return d;
}

// ---- kernel 0: clear amax accumulators ----
__global__ void vq_clear_amax_kernel() {
    if (threadIdx.x == 0) { g_amax_x = 0; g_amax_e = 0; }
}

// ---- kernel 1: fused init — counters/hist, amax_x, code norms + amax_e ----
__global__ void vq_init_kernel(const float* __restrict__ inp,
                               const float* __restrict__ emb) {
    int i = blockIdx.x * blockDim.x + threadIdx.x;
    if (i < N_ROWS) g_cnt[i] = 0;
    if (i < K_CODES) {
        g_hist[i] = 0;
        const float4* e = (const float4*)(emb + (size_t)i * D);
        float s = 0.f, m = 0.f;
        #pragma unroll
        for (int j = 0; j < 16; j++) {
            float4 v = e[j];
            s = __fadd_rn(s, __fmul_rn(v.x, v.x));
            s = __fadd_rn(s, __fmul_rn(v.y, v.y));
            s = __fadd_rn(s, __fmul_rn(v.z, v.z));
            s = __fadd_rn(s, __fmul_rn(v.w, v.w));
            m = fmaxf(m, fmaxf(fmaxf(fabsf(v.x), fabsf(v.y)),
                               fmaxf(fabsf(v.z), fabsf(v.w))));
        }
        g_norms[i] = s;
        atomicMax(&g_amax_e, __float_as_int(m));
    }
    const float4* p = (const float4*)inp;
    float m = 0.f;
    for (int j = i; j < N_ROWS * D / 4; j += gridDim.x * blockDim.x) {
        float4 v = p[j];
        m = fmaxf(m, fmaxf(fmaxf(fabsf(v.x), fabsf(v.y)),
                           fmaxf(fabsf(v.z), fabsf(v.w))));
    }
    #pragma unroll
    for (int o = 16; o > 0; o >>= 1)
        m = fmaxf(m, __shfl_xor_sync(0xffffffffu, m, o));
    if ((threadIdx.x & 31) == 0) atomicMax(&g_amax_x, __float_as_int(m));
}

// ---- kernel 2: fused quantize x + e ----
__global__ void vq_quant_kernel(const float* __restrict__ inp,
                                const float* __restrict__ emb) {
    int w = blockIdx.x * blockDim.x + threadIdx.x;
    if (w < N_ROWS * 16) {
        float amax = fmaxf(__int_as_float(g_amax_x), 1e-20f);
        float sinv = 127.f / amax;
        float4 v = ((const float4*)inp)[w];
        g_qx[w] = pack_s8x4(v.x, v.y, v.z, v.w, sinv);
    } else {
        int u = w - N_ROWS * 16;
        if (u < K_CODES * 16) {
            float amax = fmaxf(__int_as_float(g_amax_e), 1e-20f);
            float sinv = 127.f / amax;
            float4 v = ((const float4*)emb)[u];
            g_qe[u] = pack_s8x4(v.x, v.y, v.z, v.w, sinv);
        }
    }
}

// ---- kernel 3: s8 mma filter, CHUNK=64, scores stored in place ----
__global__ __launch_bounds__(F_THREADS, 8) void vq_filter_kernel() {
    __shared__ uint32_t shB[CHUNK * BPITCH];   // 64 codes * 20 words = 5KB
    __shared__ float sh_bn[K_CODES];

    const int tid = threadIdx.x;
    const int lane = tid & 31;
    const int w = tid >> 5;
    const int gq = lane >> 2;
    const int tq = lane & 3;
    const int grow0 = blockIdx.x * F_ROWS + w * 16 + gq;
    const int grow1 = grow0 + 8;

    for (int i = tid; i < K_CODES; i += F_THREADS) sh_bn[i] = g_norms[i];

    const float sx = fmaxf(__int_as_float(g_amax_x), 1e-20f) * (1.f / 127.f);
    const float se = fmaxf(__int_as_float(g_amax_e), 1e-20f) * (1.f / 127.f);
    const float f = 2.f * sx * se;

    uint32_t A0[2][2], A1[2][2];
    #pragma unroll
    for (int ks = 0; ks < 2; ks++) {
        A0[ks][0] = g_qx[grow0 * 16 + ks * 8 + tq];
        A0[ks][1] = g_qx[grow1 * 16 + ks * 8 + tq];
        A1[ks][0] = g_qx[grow0 * 16 + ks * 8 + 4 + tq];
        A1[ks][1] = g_qx[grow1 * 16 + ks * 8 + 4 + tq];
    }

    float best0 = FLT_MAX, best1 = FLT_MAX;

    for (int ch = 0; ch < NCHUNK; ch++) {
        __syncthreads();
        {
            // thread tid: code = tid/2, half = tid&1 -> 2x uint4 (8 words)
            int code = tid >> 1, half = tid & 1;
            const uint4* src = (const uint4*)&g_qe[(ch * CHUNK + code) * 16 + half * 8];
            uint4* dst = (uint4*)&shB[code * BPITCH + half * 8];
            dst[0] = src[0];
            dst[1] = src[1];
        }
        __syncthreads();

        int c[8][4];
        #pragma unroll
        for (int nt = 0; nt < 8; nt++)
            c[nt][0] = c[nt][1] = c[nt][2] = c[nt][3] = 0;

        #pragma unroll
        for (int ks = 0; ks < 2; ks++) {
            #pragma unroll
            for (int nt = 0; nt < 8; nt++) {
                int n = nt * 8 + gq;
                uint32_t b0 = shB[n * BPITCH + ks * 8 + tq];
                uint32_t b1 = shB[n * BPITCH + ks * 8 + 4 + tq];
                mma_s8(c[nt], A0[ks][0], A0[ks][1], A1[ks][0], A1[ks][1], b0, b1);
            }
        }

        // scores s = bn - f*dotq, stored IN PLACE (bit-cast into c[][]).
        const int cbase = ch * CHUNK;
        float m0 = FLT_MAX, m1 = FLT_MAX;
        #pragma unroll
        for (int nt = 0; nt < 8; nt++) {
            int col0 = cbase + nt * 8 + 2 * tq;
            float bn0 = sh_bn[col0], bn1 = sh_bn[col0 + 1];
            float s00 = fmaf(-f, (float)c[nt][0], bn0);
            float s01 = fmaf(-f, (float)c[nt][1], bn1);
            float s10 = fmaf(-f, (float)c[nt][2], bn0);
            float s11 = fmaf(-f, (float)c[nt][3], bn1);
            c[nt][0] = __float_as_int(s00);
            c[nt][1] = __float_as_int(s01);
            c[nt][2] = __float_as_int(s10);
            c[nt][3] = __float_as_int(s11);
            m0 = fminf(m0, fminf(s00, s01));
            m1 = fminf(m1, fminf(s10, s11));
        }
        m0 = fminf(m0, __shfl_xor_sync(0xffffffffu, m0, 1));
        m0 = fminf(m0, __shfl_xor_sync(0xffffffffu, m0, 2));
        m1 = fminf(m1, __shfl_xor_sync(0xffffffffu, m1, 1));
        m1 = fminf(m1, __shfl_xor_sync(0xffffffffu, m1, 2));
        best0 = fminf(best0, m0);
        best1 = fminf(best1, m1);
        const float th0 = best0 + EPS2;
        const float th1 = best1 + EPS2;

        #pragma unroll
        for (int nt = 0; nt < 8; nt++) {
            int col0 = cbase + nt * 8 + 2 * tq;
            if (__int_as_float(c[nt][0]) <= th0) {
                int s = atomicAdd(&g_cnt[grow0], 1);
                if (s < CAND_CAP) g_cand[s * N_ROWS + grow0] = (unsigned short)col0;
            }
            if (__int_as_float(c[nt][1]) <= th0) {
                int s = atomicAdd(&g_cnt[grow0], 1);
                if (s < CAND_CAP) g_cand[s * N_ROWS + grow0] = (unsigned short)(col0 + 1);
            }
            if (__int_as_float(c[nt][2]) <= th1) {
                int s = atomicAdd(&g_cnt[grow1], 1);
                if (s < CAND_CAP) g_cand[s * N_ROWS + grow1] = (unsigned short)col0;
            }
            if (__int_as_float(c[nt][3]) <= th1) {
                int s = atomicAdd(&g_cnt[grow1], 1);
                if (s < CAND_CAP) g_cand[s * N_ROWS + grow1] = (unsigned short)(col0 + 1);
            }
        }
    }
}

// ---- kernel 4: exact refine, warp-cooperative IO (unchanged from R16) ----
__global__ __launch_bounds__(R_THREADS) void vq_refine_kernel(
    const float* __restrict__ inp,
    const float* __restrict__ emb,
    float* __restrict__ out)
{
    extern __shared__ float sbuf[];
    __shared__ float sh_red[R_THREADS];

    const int tid = threadIdx.x;
    const int lane = tid & 31;
    const int wrp = tid >> 5;
    const int r = blockIdx.x * R_THREADS + tid;
    const int rb = blockIdx.x * R_THREADS + wrp * 32;
    float* buf = sbuf + wrp * 32 * RPITCH;
    const unsigned FULL = 0xffffffffu;

    for (int l = 0; l < 32; l++) {
        float2 v = *(const float2*)(inp + (size_t)(rb + l) * D + lane * 2);
        *(float2*)(buf + l * RPITCH + lane * 2) = v;
    }
    __syncwarp(FULL);
    float4 x[16];
    #pragma unroll
    for (int i = 0; i < 16; i++)
        x[i] = *(const float4*)(buf + lane * RPITCH + i * 4);
    __syncwarp(FULL);

    const float asq = exact_asq(x);

    int bi = K_CODES;
    float best = FLT_MAX;
    const int cnt = g_cnt[r];
    const bool ovf = (cnt > CAND_CAP);
    const int ccnt = ovf ? 0 : cnt;

    int rounds = ccnt;
    #pragma unroll
    for (int o = 16; o > 0; o >>= 1)
        rounds = max(rounds, __shfl_xor_sync(FULL, rounds, o));

    for (int i = 0; i < rounds; i++) {
        int myc = (i < ccnt) ? (int)g_cand[i * N_ROWS + r] : -1;
        for (int l = 0; l < 32; l++) {
            int c = __shfl_sync(FULL, myc, l);
            if (c >= 0) {
                float2 v = *(const float2*)(emb + (size_t)c * D + lane * 2);
                *(float2*)(buf + l * RPITCH + lane * 2) = v;
            }
        }
        __syncwarp(FULL);
        if (myc >= 0) {
            const float4* e = (const float4*)(buf + lane * RPITCH);
            float dot = exact_dot(x, e);
            float dist = __fadd_rn(__fmaf_rn(-2.f, dot, asq), g_norms[myc]);
            if (dist < best || (dist == best && myc < bi)) { best = dist; bi = myc; }
        }
        __syncwarp(FULL);
    }

    if (ovf) {
        best = FLT_MAX; bi = K_CODES;
        for (int c = 0; c < K_CODES; c++) {
            float dot = exact_dot(x, (const float4*)(emb + (size_t)c * D));
            float dist = __fadd_rn(__fmaf_rn(-2.f, dot, asq), g_norms[c]);
            if (dist < best) { best = dist; bi = c; }
        }
    }

    __syncwarp(FULL);
    for (int l = 0; l < 32; l++) {
        int c = __shfl_sync(FULL, bi, l);
        float2 v = *(const float2*)(emb + (size_t)c * D + lane * 2);
        *(float2*)(buf + l * RPITCH + lane * 2) = v;
    }
    __syncwarp(FULL);

    float ls = 0.f;
    {
        const float4* q4 = (const float4*)(buf + lane * RPITCH);
        #pragma unroll
        for (int i = 0; i < 16; i++) {
            float4 q = q4[i];
            float4 v = x[i];
            float d0 = v.x - q.x, d1 = v.y - q.y, d2 = v.z - q.z, d3 = v.w - q.w;
            ls = fmaf(d0, d0, ls); ls = fmaf(d1, d1, ls);
            ls = fmaf(d2, d2, ls); ls = fmaf(d3, d3, ls);
        }
    }
    for (int l = 0; l < 32; l++) {
        float2 v = *(const float2*)(buf + l * RPITCH + lane * 2);
        *(float2*)(out + (size_t)(rb + l) * D + lane * 2) = v;
    }
    out[QOFF + r] = (float)bi;
    atomicAdd(&g_hist[bi], 1);

    sh_red[tid] = ls;
    __syncthreads();
    for (int s = R_THREADS / 2; s > 0; s >>= 1) {
        if (tid < s) sh_red[tid] += sh_red[tid + s];
        __syncthreads();
    }
    if (tid == 0) g_partial[blockIdx.x] = sh_red[0];
}

// ---- kernel 5: perplexity + vq_loss ----
__global__ void vq_final_kernel(float* __restrict__ out) {
    __shared__ float sh[1024];
    const int t = threadIdx.x;

    float p = (float)g_hist[t] * (1.0f / (float)N_ROWS);
    sh[t] = p * logf(p + 1e-10f);
    __syncthreads();
    for (int s = 512; s > 0; s >>= 1) {
        if (t < s) sh[t] += sh[t + s];
        __syncthreads();
    }
    float ent = sh[0];
    __syncthreads();

    sh[t] = (t < R_BLOCKS) ? g_partial[t] : 0.f;
    __syncthreads();
    for (int s = 512; s > 0; s >>= 1) {
        if (t < s) sh[t] += sh[t + s];
        __syncthreads();
    }

    if (t == 0) {
        float m = sh[0] / (float)((size_t)N_ROWS * D);
        out[QOFF + N_ROWS]     = expf(-ent);       // perplexity
        out[QOFF + N_ROWS + 1] = m + 0.25f * m;    // commitment + beta*codebook
    }
}

extern "C" void kernel_launch(void* const* d_in, const int* in_sizes, int n_in,
                              void* d_out, int out_size) {
    const float* inp = (const float*)d_in[0];   // [131072, 64]
    const float* emb = (const float*)d_in[1];   // [1024, 64]
    float* out = (float*)d_out;

    cudaFuncSetAttribute(vq_refine_kernel,
                         cudaFuncAttributeMaxDynamicSharedMemorySize, R_SMEM);

    vq_clear_amax_kernel<<<1, 32>>>();
    vq_init_kernel<<<1024, 256>>>(inp, emb);
    vq_quant_kernel<<<8256, 256>>>(inp, emb);
    vq_filter_kernel<<<F_BLOCKS, F_THREADS>>>();
    vq_refine_kernel<<<R_BLOCKS, R_THREADS, R_SMEM>>>(inp, emb, out);
    vq_final_kernel<<<1, 1024>>>(out);
}